// round 2
// baseline (speedup 1.0000x reference)
#include <cuda_runtime.h>
#include <math.h>

#define BATCH 2
#define H0 512
#define W0 512
#define HW0 (H0*W0)
#define HW1 (256*256)
#define HW2 (128*128)

// ---------------- scratch (device globals; no allocations allowed) ----------------
__device__ float g_t1 [BATCH*32*HW0];   // conv1 out (temp)
__device__ float g_f1a[BATCH*32*HW0];   // fea1 of input_0
__device__ float g_f1b[BATCH*32*HW0];   // fea1 of input_1
__device__ float g_t2 [BATCH*64*HW1];
__device__ float g_f2a[BATCH*64*HW1];
__device__ float g_f2b[BATCH*64*HW1];
__device__ float g_t3 [BATCH*96*HW2];
__device__ float g_f3a[BATCH*96*HW2];
__device__ float g_f3b[BATCH*96*HW2];
__device__ float g_za [BATCH*HW0];      // z for direction 0
__device__ float g_zb [BATCH*HW0];      // z for direction 1
__device__ float g_zz [BATCH*HW1];      // resized z (reused)
__device__ float g_acc[BATCH*3*HW0];    // softsplat accumulator (reused)
__device__ float g_ft [BATCH*2*HW0];    // flow_t0 (reused)

// ---------------- conv3x3 + PReLU ----------------
// block: 128 threads = 128 output pixels; each thread computes 8 output channels.
// weights for these 8 channels staged in smem as [cin*9+tap][8] -> float4 pairs.
template<int STRIDE>
__global__ void conv3x3_prelu_k(const float* __restrict__ in,
                                const float* __restrict__ wgt,
                                const float* __restrict__ bias,
                                const float* __restrict__ prelu_a, int aidx,
                                float* __restrict__ out,
                                int Cin, int Cout, int Hin, int Win,
                                int Hout, int Wout)
{
    extern __shared__ float w_s[];
    const int b = blockIdx.z;
    const int co_base = blockIdx.y * 8;
    const int nW = Cin * 9;

    for (int i = threadIdx.x; i < nW * 8; i += blockDim.x) {
        int k = i & 7;
        int tap = i >> 3;
        w_s[i] = wgt[(size_t)(co_base + k) * nW + tap];
    }
    __syncthreads();

    const int p = blockIdx.x * blockDim.x + threadIdx.x;
    if (p >= Hout * Wout) return;
    const int oy = p / Wout;
    const int ox = p - oy * Wout;

    float4 acc0 = make_float4(0.f, 0.f, 0.f, 0.f);
    float4 acc1 = make_float4(0.f, 0.f, 0.f, 0.f);

    const float* inb = in + (size_t)b * Cin * Hin * Win;
    for (int ci = 0; ci < Cin; ci++) {
        const float* chan = inb + (size_t)ci * Hin * Win;
        const float* ws = w_s + ci * 72;   // 9 taps * 8
        #pragma unroll
        for (int dy = 0; dy < 3; dy++) {
            const int iy = oy * STRIDE + dy - 1;
            const bool yok = (unsigned)iy < (unsigned)Hin;
            #pragma unroll
            for (int dx = 0; dx < 3; dx++) {
                const int ix = ox * STRIDE + dx - 1;
                float v = 0.f;
                if (yok && (unsigned)ix < (unsigned)Win)
                    v = chan[iy * Win + ix];
                const float4* wp = (const float4*)(ws + (dy * 3 + dx) * 8);
                float4 wa = wp[0];
                float4 wb = wp[1];
                acc0.x += wa.x * v; acc0.y += wa.y * v;
                acc0.z += wa.z * v; acc0.w += wa.w * v;
                acc1.x += wb.x * v; acc1.y += wb.y * v;
                acc1.z += wb.z * v; acc1.w += wb.w * v;
            }
        }
    }

    const float alpha = prelu_a[aidx];
    float accs[8] = {acc0.x, acc0.y, acc0.z, acc0.w, acc1.x, acc1.y, acc1.z, acc1.w};
    #pragma unroll
    for (int k = 0; k < 8; k++) {
        float r = accs[k] + bias[co_base + k];
        r = (r >= 0.f) ? r : alpha * r;
        out[(((size_t)b * Cout + co_base + k) * Hout + oy) * Wout + ox] = r;
    }
}

// ---------------- z = param_scale * mean_c |p0 - backwarp(p1, flow)| ----------------
__global__ void compute_z_k(const float* __restrict__ i0,
                            const float* __restrict__ i1,
                            const float* __restrict__ flow,
                            const float* __restrict__ pscale,
                            float* __restrict__ z, int H, int W)
{
    const int b = blockIdx.y;
    const int p = blockIdx.x * blockDim.x + threadIdx.x;
    const int HW = H * W;
    if (p >= HW) return;
    const int y = p / W;
    const int x = p - y * W;

    const float fx = flow[((size_t)b * 2 + 0) * HW + p];
    const float fy = flow[((size_t)b * 2 + 1) * HW + p];
    float px = fminf(fmaxf((float)x + fx, 0.f), (float)(W - 1));
    float py = fminf(fmaxf((float)y + fy, 0.f), (float)(H - 1));
    float x0f = floorf(px), y0f = floorf(py);
    int x0 = (int)x0f, y0 = (int)y0f;
    int x1 = min(x0 + 1, W - 1), y1 = min(y0 + 1, H - 1);
    float wx = px - x0f, wy = py - y0f;
    float w00 = (1.f - wx) * (1.f - wy);
    float w10 = wx * (1.f - wy);
    float w01 = (1.f - wx) * wy;
    float w11 = wx * wy;

    float err = 0.f;
    #pragma unroll
    for (int c = 0; c < 3; c++) {
        const float* s = i1 + ((size_t)b * 3 + c) * HW;
        float g = s[y0 * W + x0] * w00 + s[y0 * W + x1] * w10 +
                  s[y1 * W + x0] * w01 + s[y1 * W + x1] * w11;
        float a = i0[((size_t)b * 3 + c) * HW + p];
        err += fabsf((2.f * a - 1.f) - (2.f * g - 1.f));
    }
    z[(size_t)b * HW + p] = pscale[0] * (err * (1.f / 3.f));
}

// ---------------- bilinear resize, 1 channel ----------------
__global__ void resize1_k(const float* __restrict__ in, float* __restrict__ out,
                          int Hin, int Win, int Hout, int Wout)
{
    const int b = blockIdx.y;
    const int p = blockIdx.x * blockDim.x + threadIdx.x;
    const int HWo = Hout * Wout;
    if (p >= HWo) return;
    const int y = p / Wout;
    const int x = p - y * Wout;

    const float ry = (float)Hin / (float)Hout;
    const float rx = (float)Win / (float)Wout;
    float py = fminf(fmaxf(((float)y + 0.5f) * ry - 0.5f, 0.f), (float)(Hin - 1));
    float px = fminf(fmaxf(((float)x + 0.5f) * rx - 0.5f, 0.f), (float)(Win - 1));
    float y0f = floorf(py), x0f = floorf(px);
    int y0 = (int)y0f, x0 = (int)x0f;
    int y1 = min(y0 + 1, Hin - 1), x1 = min(x0 + 1, Win - 1);
    float wy = py - y0f, wx = px - x0f;

    const float* s = in + (size_t)b * Hin * Win;
    float top = s[y0 * Win + x0] * (1.f - wx) + s[y0 * Win + x1] * wx;
    float bot = s[y1 * Win + x0] * (1.f - wx) + s[y1 * Win + x1] * wx;
    out[(size_t)b * HWo + p] = top * (1.f - wy) + bot * wy;
}

// ---------------- zero fill ----------------
__global__ void zero_k(float* __restrict__ p, int n)
{
    int i = blockIdx.x * blockDim.x + threadIdx.x;
    if (i < n) p[i] = 0.f;
}

// ---------------- softsplat scatter: ten = -f, flow = f, weight = exp(zz) ----------------
__global__ void splat_k(const float* __restrict__ flow,
                        const float* __restrict__ zz,
                        const float* __restrict__ tt, int dir,
                        float* __restrict__ acc, int H, int W)
{
    const int b = blockIdx.y;
    const int p = blockIdx.x * blockDim.x + threadIdx.x;
    const int HW = H * W;
    if (p >= HW) return;
    const int y = p / W;
    const int x = p - y * W;

    float t = tt[b];
    if (dir) t = 1.f - t;
    const float fx = t * flow[((size_t)b * 2 + 0) * HW + p];
    const float fy = t * flow[((size_t)b * 2 + 1) * HW + p];
    const float ez = expf(zz[(size_t)b * HW + p]);
    const float v0 = -fx * ez;
    const float v1 = -fy * ez;

    const float X = (float)x + fx;
    const float Y = (float)y + fy;
    const float x0f = floorf(X), y0f = floorf(Y);
    const int x0 = (int)x0f, y0 = (int)y0f;
    const float wx1 = X - x0f, wy1 = Y - y0f;
    const float wx0 = 1.f - wx1, wy0 = 1.f - wy1;

    float* a0 = acc + ((size_t)b * 3 + 0) * HW;
    float* a1 = acc + ((size_t)b * 3 + 1) * HW;
    float* a2 = acc + ((size_t)b * 3 + 2) * HW;

    int cxs[4] = {x0, x0 + 1, x0,     x0 + 1};
    int cys[4] = {y0, y0,     y0 + 1, y0 + 1};
    float cws[4] = {wx0 * wy0, wx1 * wy0, wx0 * wy1, wx1 * wy1};
    #pragma unroll
    for (int k = 0; k < 4; k++) {
        int cx = cxs[k], cy = cys[k];
        if (cx >= 0 && cx < W && cy >= 0 && cy < H) {
            int idx = cy * W + cx;
            float cw = cws[k];
            atomicAdd(a0 + idx, v0 * cw);
            atomicAdd(a1 + idx, v1 * cw);
            atomicAdd(a2 + idx, ez * cw);
        }
    }
}

// ---------------- normalize: flow_t0 = acc[0:2] / (acc[2] + eps) ----------------
__global__ void norm_k(const float* __restrict__ acc, float* __restrict__ ft,
                       int H, int W)
{
    const int b = blockIdx.y;
    const int p = blockIdx.x * blockDim.x + threadIdx.x;
    const int HW = H * W;
    if (p >= HW) return;
    float d = acc[((size_t)b * 3 + 2) * HW + p] + 1e-7f;
    float inv = 1.f / d;
    ft[((size_t)b * 2 + 0) * HW + p] = acc[((size_t)b * 3 + 0) * HW + p] * inv;
    ft[((size_t)b * 2 + 1) * HW + p] = acc[((size_t)b * 3 + 1) * HW + p] * inv;
}

// ---------------- backwarp: gather src through flow, write into output slab ----------------
__global__ void backwarp_out_k(const float* __restrict__ src,
                               const float* __restrict__ flow,
                               float* __restrict__ out,
                               int C, int H, int W, int chTot, int chOff)
{
    const int b = blockIdx.y;
    const int p = blockIdx.x * blockDim.x + threadIdx.x;
    const int HW = H * W;
    if (p >= HW) return;
    const int y = p / W;
    const int x = p - y * W;

    const float fx = flow[((size_t)b * 2 + 0) * HW + p];
    const float fy = flow[((size_t)b * 2 + 1) * HW + p];
    float px = fminf(fmaxf((float)x + fx, 0.f), (float)(W - 1));
    float py = fminf(fmaxf((float)y + fy, 0.f), (float)(H - 1));
    float x0f = floorf(px), y0f = floorf(py);
    int x0 = (int)x0f, y0 = (int)y0f;
    int x1 = min(x0 + 1, W - 1), y1 = min(y0 + 1, H - 1);
    float wx = px - x0f, wy = py - y0f;
    float w00 = (1.f - wx) * (1.f - wy);
    float w10 = wx * (1.f - wy);
    float w01 = (1.f - wx) * wy;
    float w11 = wx * wy;
    int i00 = y0 * W + x0, i10 = y0 * W + x1;
    int i01 = y1 * W + x0, i11 = y1 * W + x1;

    for (int c = 0; c < C; c++) {
        const float* s = src + ((size_t)b * C + c) * HW;
        float g = s[i00] * w00 + s[i10] * w10 + s[i01] * w01 + s[i11] * w11;
        out[((size_t)b * chTot + chOff + c) * HW + p] = g;
    }
}

// ---------------- host orchestration ----------------
static void launch_conv(const float* in, const float* w, const float* bias,
                        const float* prelu_a, int aidx, float* out,
                        int Cin, int Cout, int Hin, int Win, int stride)
{
    int Hout = Hin / stride, Wout = Win / stride;
    dim3 grid((Hout * Wout + 127) / 128, Cout / 8, BATCH);
    size_t smem = (size_t)Cin * 9 * 8 * sizeof(float);
    if (stride == 1)
        conv3x3_prelu_k<1><<<grid, 128, smem>>>(in, w, bias, prelu_a, aidx, out,
                                                Cin, Cout, Hin, Win, Hout, Wout);
    else
        conv3x3_prelu_k<2><<<grid, 128, smem>>>(in, w, bias, prelu_a, aidx, out,
                                                Cin, Cout, Hin, Win, Hout, Wout);
}

extern "C" void kernel_launch(void* const* d_in, const int* in_sizes, int n_in,
                              void* d_out, int out_size)
{
    const float* in0   = (const float*)d_in[0];
    const float* in1   = (const float*)d_in[1];
    const float* tt    = (const float*)d_in[2];
    const float* flow01[3] = {(const float*)d_in[3], (const float*)d_in[4], (const float*)d_in[5]};
    const float* flow10[3] = {(const float*)d_in[6], (const float*)d_in[7], (const float*)d_in[8]};
    const float* W_[6]  = {(const float*)d_in[9],  (const float*)d_in[11], (const float*)d_in[13],
                           (const float*)d_in[15], (const float*)d_in[17], (const float*)d_in[19]};
    const float* Bi[6]  = {(const float*)d_in[10], (const float*)d_in[12], (const float*)d_in[14],
                           (const float*)d_in[16], (const float*)d_in[18], (const float*)d_in[20]};
    const float* prelu  = (const float*)d_in[21];
    const float* pscale = (const float*)d_in[22];
    float* out = (float*)d_out;

    float *t1, *f1a, *f1b, *t2, *f2a, *f2b, *t3, *f3a, *f3b;
    float *za, *zb, *zzb, *acc, *ft;
    cudaGetSymbolAddress((void**)&t1,  g_t1);
    cudaGetSymbolAddress((void**)&f1a, g_f1a);
    cudaGetSymbolAddress((void**)&f1b, g_f1b);
    cudaGetSymbolAddress((void**)&t2,  g_t2);
    cudaGetSymbolAddress((void**)&f2a, g_f2a);
    cudaGetSymbolAddress((void**)&f2b, g_f2b);
    cudaGetSymbolAddress((void**)&t3,  g_t3);
    cudaGetSymbolAddress((void**)&f3a, g_f3a);
    cudaGetSymbolAddress((void**)&f3b, g_f3b);
    cudaGetSymbolAddress((void**)&za,  g_za);
    cudaGetSymbolAddress((void**)&zb,  g_zb);
    cudaGetSymbolAddress((void**)&zzb, g_zz);
    cudaGetSymbolAddress((void**)&acc, g_acc);
    cudaGetSymbolAddress((void**)&ft,  g_ft);

    // ---- feature pyramids ----
    // input_0
    launch_conv(in0, W_[0], Bi[0], prelu, 0, t1,  3,  32, 512, 512, 1);
    launch_conv(t1,  W_[1], Bi[1], prelu, 1, f1a, 32, 32, 512, 512, 1);
    launch_conv(f1a, W_[2], Bi[2], prelu, 2, t2,  32, 64, 512, 512, 2);
    launch_conv(t2,  W_[3], Bi[3], prelu, 3, f2a, 64, 64, 256, 256, 1);
    launch_conv(f2a, W_[4], Bi[4], prelu, 4, t3,  64, 96, 256, 256, 2);
    launch_conv(t3,  W_[5], Bi[5], prelu, 5, f3a, 96, 96, 128, 128, 1);
    // input_1
    launch_conv(in1, W_[0], Bi[0], prelu, 0, t1,  3,  32, 512, 512, 1);
    launch_conv(t1,  W_[1], Bi[1], prelu, 1, f1b, 32, 32, 512, 512, 1);
    launch_conv(f1b, W_[2], Bi[2], prelu, 2, t2,  32, 64, 512, 512, 2);
    launch_conv(t2,  W_[3], Bi[3], prelu, 3, f2b, 64, 64, 256, 256, 1);
    launch_conv(f2b, W_[4], Bi[4], prelu, 4, t3,  64, 96, 256, 256, 2);
    launch_conv(t3,  W_[5], Bi[5], prelu, 5, f3b, 96, 96, 128, 128, 1);

    // ---- z maps ----
    {
        dim3 g((HW0 + 255) / 256, BATCH);
        compute_z_k<<<g, 256>>>(in0, in1, flow01[0], pscale, za, H0, W0);
        compute_z_k<<<g, 256>>>(in1, in0, flow10[0], pscale, zb, H0, W0);
    }

    // ---- splat + backwarp, 2 directions x 3 scales ----
    const size_t levelBase[3] = {0, (size_t)BATCH * 70 * HW0,
                                 (size_t)BATCH * 70 * HW0 + (size_t)BATCH * 128 * HW1};
    const int chTot[3] = {70, 128, 192};
    const int featC[3] = {32, 64, 96};

    for (int d = 0; d < 2; d++) {
        const float* z = d ? zb : za;
        const float* img = d ? in1 : in0;
        const float* const* flows = d ? flow10 : flow01;
        const float* feats[3] = {d ? f1b : f1a, d ? f2b : f2a, d ? f3b : f3a};

        for (int s = 0; s < 3; s++) {
            const int h = 512 >> s, w = 512 >> s;
            const int hw = h * w;
            const float* zz = z;
            if (s > 0) {
                dim3 g((hw + 255) / 256, BATCH);
                resize1_k<<<g, 256>>>(z, zzb, 512, 512, h, w);
                zz = zzb;
            }
            {
                int n = BATCH * 3 * hw;
                zero_k<<<(n + 255) / 256, 256>>>(acc, n);
            }
            {
                dim3 g((hw + 255) / 256, BATCH);
                splat_k<<<g, 256>>>(flows[s], zz, tt, d, acc, h, w);
                norm_k<<<g, 256>>>(acc, ft, h, w);
                if (s == 0) {
                    // warped image -> level0
                    backwarp_out_k<<<g, 256>>>(img, ft, out, 3, h, w, 70, d ? 35 : 0);
                }
                int chOff = (s == 0) ? (d ? 38 : 3) : (d ? featC[s] : 0);
                backwarp_out_k<<<g, 256>>>(feats[s], ft, out + levelBase[s],
                                           featC[s], h, w, chTot[s], chOff);
            }
        }
    }
    (void)in_sizes; (void)n_in; (void)out_size;
}

// round 4
// speedup vs baseline: 1.3534x; 1.3534x over previous
#include <cuda_runtime.h>
#include <math.h>

#define BATCH 2
#define H0 512
#define W0 512
#define HW0 (H0*W0)
#define HW1 (256*256)
#define HW2 (128*128)

typedef unsigned long long u64;

// ---------------- scratch (device globals; no allocations allowed) ----------------
__device__ float g_t1 [BATCH*32*HW0];   // conv1 out (temp)
__device__ float g_f1a[BATCH*32*HW0];   // fea1 of input_0
__device__ float g_f1b[BATCH*32*HW0];   // fea1 of input_1
__device__ float g_t2 [BATCH*64*HW1];
__device__ float g_f2a[BATCH*64*HW1];
__device__ float g_f2b[BATCH*64*HW1];
__device__ float g_t3 [BATCH*96*HW2];
__device__ float g_f3a[BATCH*96*HW2];
__device__ float g_f3b[BATCH*96*HW2];
__device__ float g_za [BATCH*HW0];      // z for direction 0
__device__ float g_zb [BATCH*HW0];      // z for direction 1
__device__ float g_zz [BATCH*HW1];      // resized z (reused)
__device__ float g_acc[BATCH*3*HW0];    // softsplat accumulator (reused)
__device__ float g_ft [BATCH*2*HW0];    // flow_t0 (reused)

// ---------------- packed f32x2 helpers ----------------
__device__ __forceinline__ u64 dup2(float v) {
    u64 r; asm("mov.b64 %0, {%1, %1};" : "=l"(r) : "f"(v)); return r;
}
__device__ __forceinline__ u64 pack2(float lo, float hi) {
    u64 r; asm("mov.b64 %0, {%1, %2};" : "=l"(r) : "f"(lo), "f"(hi)); return r;
}
__device__ __forceinline__ void ffma2(u64 &acc, u64 w, u64 v) {
    asm("fma.rn.f32x2 %0, %1, %2, %0;" : "+l"(acc) : "l"(w), "l"(v));
}
__device__ __forceinline__ float2 unp2(u64 a) {
    float2 r; asm("mov.b64 {%0, %1}, %2;" : "=f"(r.x), "=f"(r.y) : "l"(a)); return r;
}

// ---------------- conv3x3 + PReLU, v2 ----------------
// 128 threads/block; each thread computes 4 consecutive output pixels x 8 output
// channels, with channels packed in pairs into f32x2 accumulators (FFMA2 path).
// Weights staged in smem as channel-pair u64s; reads are warp-uniform (broadcast).
template<int STRIDE>
__global__ void __launch_bounds__(128)
conv3x3_prelu_v2(const float* __restrict__ in, const float* __restrict__ wgt,
                 const float* __restrict__ bias, const float* __restrict__ prelu_a,
                 int aidx, float* __restrict__ out,
                 int Cin, int Cout, int Hin, int Win, int Hout, int Wout)
{
    extern __shared__ u64 w_s[];   // [Cin][9 taps][4 channel-pairs]
    const int tid = threadIdx.x;
    const int b = blockIdx.z;
    const int co_base = blockIdx.y * 8;
    const int nW = Cin * 9;

    for (int i = tid; i < Cin * 36; i += 128) {
        int q = i & 3, rest = i >> 2;
        int tap = rest % 9, ci = rest / 9;
        float lo = wgt[(size_t)(co_base + 2*q    ) * nW + ci*9 + tap];
        float hi = wgt[(size_t)(co_base + 2*q + 1) * nW + ci*9 + tap];
        w_s[i] = pack2(lo, hi);
    }
    __syncthreads();

    const int base = (blockIdx.x * 128 + tid) * 4;   // 4 consecutive pixels, same row
    const int oy = base / Wout;
    const int ox = base - oy * Wout;
    constexpr int NV = 4 * STRIDE + 2;               // input values per row needed

    u64 acc[4][4];
    #pragma unroll
    for (int p = 0; p < 4; p++)
        #pragma unroll
        for (int q = 0; q < 4; q++) acc[p][q] = 0ULL;

    const int HWin = Hin * Win;
    const float* chan = in + (size_t)b * Cin * HWin;
    const int ix0 = ox * STRIDE - 1;
    const int iy0 = oy * STRIDE - 1;

    for (int ci = 0; ci < Cin; ci++, chan += HWin) {
        const u64* wrow = w_s + ci * 36;
        #pragma unroll
        for (int r = 0; r < 3; r++) {
            const int iy = iy0 + r;
            if ((unsigned)iy >= (unsigned)Hin) continue;
            const float* row = chan + iy * Win;
            u64 vd[NV];
            #pragma unroll
            for (int i = 0; i < NV; i++) {
                int ix = ix0 + i;
                float v = ((unsigned)ix < (unsigned)Win) ? __ldg(row + ix) : 0.f;
                vd[i] = dup2(v);
            }
            #pragma unroll
            for (int dx = 0; dx < 3; dx++) {
                const u64* wt = wrow + (r * 3 + dx) * 4;
                u64 w0 = wt[0], w1 = wt[1], w2 = wt[2], w3 = wt[3];
                #pragma unroll
                for (int p = 0; p < 4; p++) {
                    u64 vv = vd[p * STRIDE + dx];
                    ffma2(acc[p][0], w0, vv);
                    ffma2(acc[p][1], w1, vv);
                    ffma2(acc[p][2], w2, vv);
                    ffma2(acc[p][3], w3, vv);
                }
            }
        }
    }

    const float alpha = prelu_a[aidx];
    const int HWout = Hout * Wout;
    float* ob = out + ((size_t)b * Cout + co_base) * HWout + base;
    #pragma unroll
    for (int q = 0; q < 4; q++) {
        float blo = bias[co_base + 2*q], bhi = bias[co_base + 2*q + 1];
        float4 olo, ohi;
        float* plo = &olo.x; float* phi = &ohi.x;
        #pragma unroll
        for (int p = 0; p < 4; p++) {
            float2 a = unp2(acc[p][q]);
            float rl = a.x + blo; rl = (rl >= 0.f) ? rl : alpha * rl;
            float rh = a.y + bhi; rh = (rh >= 0.f) ? rh : alpha * rh;
            plo[p] = rl; phi[p] = rh;
        }
        *(float4*)(ob + (size_t)(2*q    ) * HWout) = olo;
        *(float4*)(ob + (size_t)(2*q + 1) * HWout) = ohi;
    }
}

// ---------------- z = param_scale * mean_c |p0 - backwarp(p1, flow)| ----------------
__global__ void compute_z_k(const float* __restrict__ i0,
                            const float* __restrict__ i1,
                            const float* __restrict__ flow,
                            const float* __restrict__ pscale,
                            float* __restrict__ z, int H, int W)
{
    const int b = blockIdx.y;
    const int p = blockIdx.x * blockDim.x + threadIdx.x;
    const int HW = H * W;
    if (p >= HW) return;
    const int y = p / W;
    const int x = p - y * W;

    const float fx = flow[((size_t)b * 2 + 0) * HW + p];
    const float fy = flow[((size_t)b * 2 + 1) * HW + p];
    float px = fminf(fmaxf((float)x + fx, 0.f), (float)(W - 1));
    float py = fminf(fmaxf((float)y + fy, 0.f), (float)(H - 1));
    float x0f = floorf(px), y0f = floorf(py);
    int x0 = (int)x0f, y0 = (int)y0f;
    int x1 = min(x0 + 1, W - 1), y1 = min(y0 + 1, H - 1);
    float wx = px - x0f, wy = py - y0f;
    float w00 = (1.f - wx) * (1.f - wy);
    float w10 = wx * (1.f - wy);
    float w01 = (1.f - wx) * wy;
    float w11 = wx * wy;

    float err = 0.f;
    #pragma unroll
    for (int c = 0; c < 3; c++) {
        const float* s = i1 + ((size_t)b * 3 + c) * HW;
        float g = s[y0 * W + x0] * w00 + s[y0 * W + x1] * w10 +
                  s[y1 * W + x0] * w01 + s[y1 * W + x1] * w11;
        float a = i0[((size_t)b * 3 + c) * HW + p];
        err += fabsf((2.f * a - 1.f) - (2.f * g - 1.f));
    }
    z[(size_t)b * HW + p] = pscale[0] * (err * (1.f / 3.f));
}

// ---------------- bilinear resize, 1 channel ----------------
__global__ void resize1_k(const float* __restrict__ in, float* __restrict__ out,
                          int Hin, int Win, int Hout, int Wout)
{
    const int b = blockIdx.y;
    const int p = blockIdx.x * blockDim.x + threadIdx.x;
    const int HWo = Hout * Wout;
    if (p >= HWo) return;
    const int y = p / Wout;
    const int x = p - y * Wout;

    const float ry = (float)Hin / (float)Hout;
    const float rx = (float)Win / (float)Wout;
    float py = fminf(fmaxf(((float)y + 0.5f) * ry - 0.5f, 0.f), (float)(Hin - 1));
    float px = fminf(fmaxf(((float)x + 0.5f) * rx - 0.5f, 0.f), (float)(Win - 1));
    float y0f = floorf(py), x0f = floorf(px);
    int y0 = (int)y0f, x0 = (int)x0f;
    int y1 = min(y0 + 1, Hin - 1), x1 = min(x0 + 1, Win - 1);
    float wy = py - y0f, wx = px - x0f;

    const float* s = in + (size_t)b * Hin * Win;
    float top = s[y0 * Win + x0] * (1.f - wx) + s[y0 * Win + x1] * wx;
    float bot = s[y1 * Win + x0] * (1.f - wx) + s[y1 * Win + x1] * wx;
    out[(size_t)b * HWo + p] = top * (1.f - wy) + bot * wy;
}

// ---------------- softsplat scatter: ten = -f, flow = f, weight = exp(zz) ----------------
__global__ void splat_k(const float* __restrict__ flow,
                        const float* __restrict__ zz,
                        const float* __restrict__ tt, int dir,
                        float* __restrict__ acc, int H, int W)
{
    const int b = blockIdx.y;
    const int p = blockIdx.x * blockDim.x + threadIdx.x;
    const int HW = H * W;
    if (p >= HW) return;
    const int y = p / W;
    const int x = p - y * W;

    float t = tt[b];
    if (dir) t = 1.f - t;
    const float fx = t * flow[((size_t)b * 2 + 0) * HW + p];
    const float fy = t * flow[((size_t)b * 2 + 1) * HW + p];
    const float ez = expf(zz[(size_t)b * HW + p]);
    const float v0 = -fx * ez;
    const float v1 = -fy * ez;

    const float X = (float)x + fx;
    const float Y = (float)y + fy;
    const float x0f = floorf(X), y0f = floorf(Y);
    const int x0 = (int)x0f, y0 = (int)y0f;
    const float wx1 = X - x0f, wy1 = Y - y0f;
    const float wx0 = 1.f - wx1, wy0 = 1.f - wy1;

    float* a0 = acc + ((size_t)b * 3 + 0) * HW;
    float* a1 = acc + ((size_t)b * 3 + 1) * HW;
    float* a2 = acc + ((size_t)b * 3 + 2) * HW;

    int cxs[4] = {x0, x0 + 1, x0,     x0 + 1};
    int cys[4] = {y0, y0,     y0 + 1, y0 + 1};
    float cws[4] = {wx0 * wy0, wx1 * wy0, wx0 * wy1, wx1 * wy1};
    #pragma unroll
    for (int k = 0; k < 4; k++) {
        int cx = cxs[k], cy = cys[k];
        if (cx >= 0 && cx < W && cy >= 0 && cy < H) {
            int idx = cy * W + cx;
            float cw = cws[k];
            atomicAdd(a0 + idx, v0 * cw);
            atomicAdd(a1 + idx, v1 * cw);
            atomicAdd(a2 + idx, ez * cw);
        }
    }
}

// ---------------- normalize: flow_t0 = acc[0:2] / (acc[2] + eps) ----------------
__global__ void norm_k(const float* __restrict__ acc, float* __restrict__ ft,
                       int H, int W)
{
    const int b = blockIdx.y;
    const int p = blockIdx.x * blockDim.x + threadIdx.x;
    const int HW = H * W;
    if (p >= HW) return;
    float d = acc[((size_t)b * 3 + 2) * HW + p] + 1e-7f;
    float inv = 1.f / d;
    ft[((size_t)b * 2 + 0) * HW + p] = acc[((size_t)b * 3 + 0) * HW + p] * inv;
    ft[((size_t)b * 2 + 1) * HW + p] = acc[((size_t)b * 3 + 1) * HW + p] * inv;
}

// ---------------- backwarp: gather src through flow, write into output slab ----------------
__global__ void backwarp_out_k(const float* __restrict__ src,
                               const float* __restrict__ flow,
                               float* __restrict__ out,
                               int C, int H, int W, int chTot, int chOff)
{
    const int b = blockIdx.y;
    const int p = blockIdx.x * blockDim.x + threadIdx.x;
    const int HW = H * W;
    if (p >= HW) return;
    const int y = p / W;
    const int x = p - y * W;

    const float fx = flow[((size_t)b * 2 + 0) * HW + p];
    const float fy = flow[((size_t)b * 2 + 1) * HW + p];
    float px = fminf(fmaxf((float)x + fx, 0.f), (float)(W - 1));
    float py = fminf(fmaxf((float)y + fy, 0.f), (float)(H - 1));
    float x0f = floorf(px), y0f = floorf(py);
    int x0 = (int)x0f, y0 = (int)y0f;
    int x1 = min(x0 + 1, W - 1), y1 = min(y0 + 1, H - 1);
    float wx = px - x0f, wy = py - y0f;
    float w00 = (1.f - wx) * (1.f - wy);
    float w10 = wx * (1.f - wy);
    float w01 = (1.f - wx) * wy;
    float w11 = wx * wy;
    int i00 = y0 * W + x0, i10 = y0 * W + x1;
    int i01 = y1 * W + x0, i11 = y1 * W + x1;

    for (int c = 0; c < C; c++) {
        const float* s = src + ((size_t)b * C + c) * HW;
        float g = s[i00] * w00 + s[i10] * w10 + s[i01] * w01 + s[i11] * w11;
        out[((size_t)b * chTot + chOff + c) * HW + p] = g;
    }
}

// ---------------- host orchestration ----------------
static void launch_conv(const float* in, const float* w, const float* bias,
                        const float* prelu_a, int aidx, float* out,
                        int Cin, int Cout, int Hin, int Win, int stride)
{
    int Hout = Hin / stride, Wout = Win / stride;
    dim3 grid((Hout * Wout) / 512, Cout / 8, BATCH);
    size_t smem = (size_t)Cin * 36 * sizeof(u64);
    if (stride == 1)
        conv3x3_prelu_v2<1><<<grid, 128, smem>>>(in, w, bias, prelu_a, aidx, out,
                                                 Cin, Cout, Hin, Win, Hout, Wout);
    else
        conv3x3_prelu_v2<2><<<grid, 128, smem>>>(in, w, bias, prelu_a, aidx, out,
                                                 Cin, Cout, Hin, Win, Hout, Wout);
}

extern "C" void kernel_launch(void* const* d_in, const int* in_sizes, int n_in,
                              void* d_out, int out_size)
{
    const float* in0   = (const float*)d_in[0];
    const float* in1   = (const float*)d_in[1];
    const float* tt    = (const float*)d_in[2];
    const float* flow01[3] = {(const float*)d_in[3], (const float*)d_in[4], (const float*)d_in[5]};
    const float* flow10[3] = {(const float*)d_in[6], (const float*)d_in[7], (const float*)d_in[8]};
    const float* W_[6]  = {(const float*)d_in[9],  (const float*)d_in[11], (const float*)d_in[13],
                           (const float*)d_in[15], (const float*)d_in[17], (const float*)d_in[19]};
    const float* Bi[6]  = {(const float*)d_in[10], (const float*)d_in[12], (const float*)d_in[14],
                           (const float*)d_in[16], (const float*)d_in[18], (const float*)d_in[20]};
    const float* prelu  = (const float*)d_in[21];
    const float* pscale = (const float*)d_in[22];
    float* out = (float*)d_out;

    float *t1, *f1a, *f1b, *t2, *f2a, *f2b, *t3, *f3a, *f3b;
    float *za, *zb, *zzb, *acc, *ft;
    cudaGetSymbolAddress((void**)&t1,  g_t1);
    cudaGetSymbolAddress((void**)&f1a, g_f1a);
    cudaGetSymbolAddress((void**)&f1b, g_f1b);
    cudaGetSymbolAddress((void**)&t2,  g_t2);
    cudaGetSymbolAddress((void**)&f2a, g_f2a);
    cudaGetSymbolAddress((void**)&f2b, g_f2b);
    cudaGetSymbolAddress((void**)&t3,  g_t3);
    cudaGetSymbolAddress((void**)&f3a, g_f3a);
    cudaGetSymbolAddress((void**)&f3b, g_f3b);
    cudaGetSymbolAddress((void**)&za,  g_za);
    cudaGetSymbolAddress((void**)&zb,  g_zb);
    cudaGetSymbolAddress((void**)&zzb, g_zz);
    cudaGetSymbolAddress((void**)&acc, g_acc);
    cudaGetSymbolAddress((void**)&ft,  g_ft);

    // ---- feature pyramids ----
    launch_conv(in0, W_[0], Bi[0], prelu, 0, t1,  3,  32, 512, 512, 1);
    launch_conv(t1,  W_[1], Bi[1], prelu, 1, f1a, 32, 32, 512, 512, 1);
    launch_conv(f1a, W_[2], Bi[2], prelu, 2, t2,  32, 64, 512, 512, 2);
    launch_conv(t2,  W_[3], Bi[3], prelu, 3, f2a, 64, 64, 256, 256, 1);
    launch_conv(f2a, W_[4], Bi[4], prelu, 4, t3,  64, 96, 256, 256, 2);
    launch_conv(t3,  W_[5], Bi[5], prelu, 5, f3a, 96, 96, 128, 128, 1);

    launch_conv(in1, W_[0], Bi[0], prelu, 0, t1,  3,  32, 512, 512, 1);
    launch_conv(t1,  W_[1], Bi[1], prelu, 1, f1b, 32, 32, 512, 512, 1);
    launch_conv(f1b, W_[2], Bi[2], prelu, 2, t2,  32, 64, 512, 512, 2);
    launch_conv(t2,  W_[3], Bi[3], prelu, 3, f2b, 64, 64, 256, 256, 1);
    launch_conv(f2b, W_[4], Bi[4], prelu, 4, t3,  64, 96, 256, 256, 2);
    launch_conv(t3,  W_[5], Bi[5], prelu, 5, f3b, 96, 96, 128, 128, 1);

    // ---- z maps ----
    {
        dim3 g((HW0 + 255) / 256, BATCH);
        compute_z_k<<<g, 256>>>(in0, in1, flow01[0], pscale, za, H0, W0);
        compute_z_k<<<g, 256>>>(in1, in0, flow10[0], pscale, zb, H0, W0);
    }

    // ---- splat + backwarp, 2 directions x 3 scales ----
    const size_t levelBase[3] = {0, (size_t)BATCH * 70 * HW0,
                                 (size_t)BATCH * 70 * HW0 + (size_t)BATCH * 128 * HW1};
    const int chTot[3] = {70, 128, 192};
    const int featC[3] = {32, 64, 96};

    for (int d = 0; d < 2; d++) {
        const float* z = d ? zb : za;
        const float* img = d ? in1 : in0;
        const float* const* flows = d ? flow10 : flow01;
        const float* feats[3] = {d ? f1b : f1a, d ? f2b : f2a, d ? f3b : f3a};

        for (int s = 0; s < 3; s++) {
            const int h = 512 >> s, w = 512 >> s;
            const int hw = h * w;
            const float* zz = z;
            if (s > 0) {
                dim3 g((hw + 255) / 256, BATCH);
                resize1_k<<<g, 256>>>(z, zzb, 512, 512, h, w);
                zz = zzb;
            }
            cudaMemsetAsync(acc, 0, (size_t)BATCH * 3 * hw * sizeof(float));
            {
                dim3 g((hw + 255) / 256, BATCH);
                splat_k<<<g, 256>>>(flows[s], zz, tt, d, acc, h, w);
                norm_k<<<g, 256>>>(acc, ft, h, w);
                if (s == 0) {
                    backwarp_out_k<<<g, 256>>>(img, ft, out, 3, h, w, 70, d ? 35 : 0);
                }
                int chOff = (s == 0) ? (d ? 38 : 3) : (d ? featC[s] : 0);
                backwarp_out_k<<<g, 256>>>(feats[s], ft, out + levelBase[s],
                                           featC[s], h, w, chTot[s], chOff);
            }
        }
    }
    (void)in_sizes; (void)n_in; (void)out_size;
}